// round 8
// baseline (speedup 1.0000x reference)
#include <cuda_runtime.h>
#include <cstdint>
#include <cstddef>

#define BATCH 256
#define SEQ   512
#define HID   256
#define G3    768
#define IN_DIM 65
#define RDIM  64

#define OUT_N  ((size_t)BATCH * SEQ * RDIM)   //  8,388,608
#define HID_N  ((size_t)BATCH * SEQ * HID)    // 33,554,432
#define TOT_N  (OUT_N + HID_N)                // 41,943,040

// ---------------- static scratch -------------------------------------------
// gate-interleaved gi: gi4[b][t][u][gate(r,z,n,pad)]
__device__ float g_gi4[(size_t)BATCH * SEQ * HID * 4];   // 536 MB
__device__ float g_hid[HID_N];                           // fallback rnn_hid
__device__ float g_out[OUT_N];                           // fallback out

// ---------------- helpers ----------------
__device__ __forceinline__ void ffma2(unsigned long long &acc,
                                      unsigned long long a, unsigned long long b) {
    asm("fma.rn.f32x2 %0, %1, %2, %0;" : "+l"(acc) : "l"(a), "l"(b));
}
__device__ __forceinline__ float f2sum(unsigned long long a) {
    unsigned int lo, hi;
    asm("mov.b64 {%0,%1}, %2;" : "=r"(lo), "=r"(hi) : "l"(a));
    return __uint_as_float(lo) + __uint_as_float(hi);
}
__device__ __forceinline__ float sigmoidf_(float x) {
    return __fdividef(1.0f, 1.0f + __expf(-x));
}

// =====================================================================
// Kernel 1: gi4 = stimulus @ W_ih^T + b_ih, gate-interleaved output.
// Tile: 16 bt-rows x 384 g ; 512 threads ; 112 KB SMEM -> 2 CTAs/SM.
// =====================================================================
#define GI_TBT 16
#define GI_GT  384
#define GI_PITCH 70
#define GI_SMEM ((GI_GT * GI_PITCH + GI_TBT * GI_PITCH) * 4)   // 112,000 B

__global__ void __launch_bounds__(512, 2)
gi_kernel(const float* __restrict__ stim,
          const float* __restrict__ W_ih,
          const float* __restrict__ b_ih)
{
    extern __shared__ float sm[];
    float* w_s = sm;                      // [384][GI_PITCH]
    float* x_s = sm + GI_GT * GI_PITCH;   // [16][GI_PITCH]

    const int tid = threadIdx.x;
    const int bt0 = (blockIdx.x >> 1) * GI_TBT;
    const int g0  = (blockIdx.x & 1) * GI_GT;

    for (int idx = tid; idx < GI_GT * IN_DIM; idx += 512) {
        int g = idx / IN_DIM, k = idx - g * IN_DIM;
        w_s[g * GI_PITCH + k] = W_ih[(size_t)(g0 + g) * IN_DIM + k];
    }
    for (int idx = tid; idx < GI_TBT * IN_DIM; idx += 512) {
        int r = idx / IN_DIM, c = idx - r * IN_DIM;
        x_s[r * GI_PITCH + c] = stim[(size_t)(bt0 + r) * IN_DIM + c];
    }
    __syncthreads();

    const int gx = tid & 63;        // g_local = gx + 64*i, i < 6
    const int by = tid >> 6;        // 0..7 -> bt rows by*2, by*2+1

    unsigned long long acc0[6], acc1[6];
#pragma unroll
    for (int i = 0; i < 6; ++i) { acc0[i] = 0ull; acc1[i] = 0ull; }

    const float* x0 = x_s + (by * 2) * GI_PITCH;
    const float* x1 = x_s + (by * 2 + 1) * GI_PITCH;

#pragma unroll 8
    for (int k = 0; k < 64; k += 2) {
        unsigned long long xv0 = *(const unsigned long long*)(x0 + k);
        unsigned long long xv1 = *(const unsigned long long*)(x1 + k);
#pragma unroll
        for (int i = 0; i < 6; ++i) {
            unsigned long long wv =
                *(const unsigned long long*)(w_s + (gx + 64 * i) * GI_PITCH + k);
            ffma2(acc0[i], xv0, wv);
            ffma2(acc1[i], xv1, wv);
        }
    }
    const float x0l = x0[64], x1l = x1[64];

    const size_t bt_a = (size_t)(bt0 + by * 2);
#pragma unroll
    for (int i = 0; i < 6; ++i) {
        int   gl   = gx + 64 * i;
        int   gg   = g0 + gl;                    // global gate-row 0..767
        int   gate = gg >> 8;                    // 0=r,1=z,2=n
        int   unit = gg & 255;
        float w64  = w_s[gl * GI_PITCH + 64];
        float bias = b_ih[gg];
        g_gi4[(bt_a)     * 1024 + unit * 4 + gate] = f2sum(acc0[i]) + x0l * w64 + bias;
        g_gi4[(bt_a + 1) * 1024 + unit * 4 + gate] = f2sum(acc1[i]) + x1l * w64 + bias;
    }
}

// =====================================================================
// Kernel 2: GRU recurrence — 4-CTA cluster, k-quad layouts:
//   Ws[g][k4][u][4]  (196,608 B)  w load = LDS.128, 8 distinct u,
//                                  banks 4u..4u+3 -> conflict-free
//   hq[buf][k4][b][4] (16,384 B)  h load = LDS.128, 4 distinct b-slots,
//                                  conflict-free, 8-way broadcast
// thread (bx=tid&3, u=tid>>2): unit u, batch rows 2bx, 2bx+1.
// =====================================================================
#define CLUSTER 4
#define HT 64
#define BT 8
#define GRU_SMEM (3 * 64 * 64 * 4 * 4 + 2 * 64 * 8 * 4 * 4)   // 212,992 B

__global__ void __cluster_dims__(CLUSTER, 1, 1) __launch_bounds__(256, 1)
gru_kernel(const float* __restrict__ W_hh,
           const float* __restrict__ b_hh,
           float* __restrict__ out_hid)
{
    extern __shared__ float smem[];
    float* Ws = smem;            // [3][64][64][4]  offset(g,k4,u,j)=g*16384+k4*256+u*4+j
    float* hq = smem + 49152;    // [2][64][8][4]   offset(buf,k4,b,j)=buf*2048+k4*32+b*4+j

    const int tid = threadIdx.x;
    unsigned int rank;
    asm("mov.u32 %0, %%cluster_ctarank;" : "=r"(rank));
    const int cl     = blockIdx.x / CLUSTER;
    const int h_off  = (int)rank * HT;
    const int b_base = cl * BT;

    // stage W_hh slice into k-quad layout
    for (int idx = tid; idx < 3 * HT * HID; idx += 256) {
        int g   = idx >> 14;          // /16384
        int rem = idx & 16383;
        int u   = rem >> 8;
        int k   = rem & 255;
        Ws[g * 16384 + (k >> 2) * 256 + u * 4 + (k & 3)] =
            W_hh[(size_t)(g * HID + h_off + u) * HID + k];
    }
    // h0 = 0.1 (buffer 0; buffer 1 fully rewritten every step)
    for (int idx = tid; idx < 2048; idx += 256) hq[idx] = 0.1f;
    __syncthreads();

    const int bx = tid & 3;
    const int u  = tid >> 2;
    const int b0 = 2 * bx, b1 = 2 * bx + 1;
    const int ug = h_off + u;

    const float bhr = b_hh[ug];
    const float bhz = b_hh[HID + ug];
    const float bhn = b_hh[2 * HID + ug];

    const float* gi0 = g_gi4 + (size_t)(b_base + b0) * SEQ * 1024 + ug * 4;
    const float* gi1 = g_gi4 + (size_t)(b_base + b1) * SEQ * 1024 + ug * 4;
    float* o0 = out_hid + (size_t)(b_base + b0) * SEQ * HID + ug;
    float* o1 = out_hid + (size_t)(b_base + b1) * SEQ * HID + ug;

    const unsigned int hq_u32 = (unsigned int)__cvta_generic_to_shared(hq);
    const int hpos = (ug >> 2) * 32 + (ug & 3);   // + b*4 selects batch row

    const float* wr_p = Ws + 0 * 16384 + u * 4;
    const float* wz_p = Ws + 1 * 16384 + u * 4;
    const float* wn_p = Ws + 2 * 16384 + u * 4;

    int buf = 0;
    for (int t = 0; t < SEQ; ++t) {
        // prefetch gi (consumed after the ~3K-cycle dot loop)
        const float4 gv0 = *(const float4*)gi0;   // (r,z,n,pad)
        const float4 gv1 = *(const float4*)gi1;

        const float* hb = hq + buf * 2048;
        float h_old0 = hb[hpos + b0 * 4];
        float h_old1 = hb[hpos + b1 * 4];

        unsigned long long ar0 = 0, az0 = 0, an0 = 0;
        unsigned long long ar1 = 0, az1 = 0, an1 = 0;
#pragma unroll 4
        for (int k4 = 0; k4 < 64; ++k4) {
            ulonglong2 h0 = *(const ulonglong2*)(hb + k4 * 32 + b0 * 4);
            ulonglong2 h1 = *(const ulonglong2*)(hb + k4 * 32 + b1 * 4);
            ulonglong2 wr = *(const ulonglong2*)(wr_p + k4 * 256);
            ulonglong2 wz = *(const ulonglong2*)(wz_p + k4 * 256);
            ulonglong2 wn = *(const ulonglong2*)(wn_p + k4 * 256);
            ffma2(ar0, h0.x, wr.x); ffma2(ar0, h0.y, wr.y);
            ffma2(az0, h0.x, wz.x); ffma2(az0, h0.y, wz.y);
            ffma2(an0, h0.x, wn.x); ffma2(an0, h0.y, wn.y);
            ffma2(ar1, h1.x, wr.x); ffma2(ar1, h1.y, wr.y);
            ffma2(az1, h1.x, wz.x); ffma2(az1, h1.y, wz.y);
            ffma2(an1, h1.x, wn.x); ffma2(an1, h1.y, wn.y);
        }
        float sr0 = f2sum(ar0) + bhr, sz0 = f2sum(az0) + bhz, sn0 = f2sum(an0) + bhn;
        float sr1 = f2sum(ar1) + bhr, sz1 = f2sum(az1) + bhz, sn1 = f2sum(an1) + bhn;

        float r0 = sigmoidf_(gv0.x + sr0);
        float z0 = sigmoidf_(gv0.y + sz0);
        float n0 = fmaxf(fmaf(r0, sn0, gv0.z), 0.0f);
        float hn0 = fmaf(z0, h_old0 - n0, n0);       // (1-z)n + z*h

        float r1 = sigmoidf_(gv1.x + sr1);
        float z1 = sigmoidf_(gv1.y + sz1);
        float n1 = fmaxf(fmaf(r1, sn1, gv1.z), 0.0f);
        float hn1 = fmaf(z1, h_old1 - n1, n1);

        o0[0] = hn0;
        o1[0] = hn1;

        // broadcast new h into next buffer of ALL cluster CTAs (incl. self)
        const int nbuf = buf ^ 1;
        unsigned int a0 = hq_u32 + (unsigned int)((nbuf * 2048 + hpos + b0 * 4) * 4);
        unsigned int a1 = hq_u32 + (unsigned int)((nbuf * 2048 + hpos + b1 * 4) * 4);
#pragma unroll
        for (int rr = 0; rr < CLUSTER; ++rr) {
            unsigned int ra0, ra1;
            asm("mapa.shared::cluster.u32 %0, %1, %2;" : "=r"(ra0) : "r"(a0), "r"(rr));
            asm("mapa.shared::cluster.u32 %0, %1, %2;" : "=r"(ra1) : "r"(a1), "r"(rr));
            asm volatile("st.shared::cluster.f32 [%0], %1;" :: "r"(ra0), "f"(hn0) : "memory");
            asm volatile("st.shared::cluster.f32 [%0], %1;" :: "r"(ra1), "f"(hn1) : "memory");
        }
        // arrive(release) / wait(acquire): one cluster sync per step
        asm volatile("barrier.cluster.arrive.aligned;" ::: "memory");
        asm volatile("barrier.cluster.wait.aligned;"   ::: "memory");

        buf = nbuf;
        gi0 += 1024; gi1 += 1024; o0 += HID; o1 += HID;
    }
}

// =====================================================================
// Kernel 3: out = relu(rnn_hid @ W_out^T + b_out)   [B*T,256] x [256,64]
// =====================================================================
#define HD_TBT 64
#define HD_HPITCH 260
#define HD_WPITCH 258
#define HD_SMEM ((HD_TBT * HD_HPITCH + RDIM * HD_WPITCH) * 4)

__global__ void __launch_bounds__(256, 1)
head_kernel(const float* __restrict__ hid,
            const float* __restrict__ W_out,
            const float* __restrict__ b_out,
            float* __restrict__ out)
{
    extern __shared__ float sm[];
    float* h_s = sm;                      // [64][HD_HPITCH]
    float* w_s = sm + HD_TBT * HD_HPITCH; // [64][HD_WPITCH]

    const int tid = threadIdx.x;
    const int bt0 = blockIdx.x * HD_TBT;

    for (int idx = tid; idx < HD_TBT * HID; idx += 256) {
        int r = idx >> 8, c = idx & 255;
        h_s[r * HD_HPITCH + c] = hid[(size_t)(bt0 + r) * HID + c];
    }
    for (int idx = tid; idx < RDIM * HID; idx += 256) {
        int r = idx >> 8, c = idx & 255;
        w_s[r * HD_WPITCH + c] = W_out[idx];
    }
    __syncthreads();

    const int rx = tid & 15;   // r  = rx + 16*i, i < 4
    const int by = tid >> 4;   // bt = bt0 + by*4 + j, j < 4

    unsigned long long acc[4][4];
#pragma unroll
    for (int j = 0; j < 4; ++j)
#pragma unroll
        for (int i = 0; i < 4; ++i) acc[j][i] = 0ull;

#pragma unroll 4
    for (int k = 0; k < HID; k += 2) {
        unsigned long long hv[4], wv[4];
#pragma unroll
        for (int j = 0; j < 4; ++j)
            hv[j] = *(const unsigned long long*)(h_s + (by * 4 + j) * HD_HPITCH + k);
#pragma unroll
        for (int i = 0; i < 4; ++i)
            wv[i] = *(const unsigned long long*)(w_s + (rx + 16 * i) * HD_WPITCH + k);
#pragma unroll
        for (int j = 0; j < 4; ++j)
#pragma unroll
            for (int i = 0; i < 4; ++i) ffma2(acc[j][i], hv[j], wv[i]);
    }

#pragma unroll
    for (int j = 0; j < 4; ++j) {
        size_t row = (size_t)(bt0 + by * 4 + j) * RDIM;
#pragma unroll
        for (int i = 0; i < 4; ++i) {
            int   r = rx + 16 * i;
            float v = f2sum(acc[j][i]) + b_out[r];
            out[row + r] = fmaxf(v, 0.0f);
        }
    }
}

// =====================================================================
// launch — inputs bound BY ELEMENT COUNT; output layout from out_size.
// =====================================================================
extern "C" void kernel_launch(void* const* d_in, const int* in_sizes, int n_in,
                              void* d_out, int out_size)
{
    const float *stim = nullptr, *W_ih = nullptr, *W_hh = nullptr,
                *b_ih = nullptr, *b_hh = nullptr, *W_out = nullptr, *b_out = nullptr;

    for (int i = 0; i < n_in; ++i) {
        const float* p = (const float*)d_in[i];
        switch (in_sizes[i]) {
            case BATCH * SEQ * IN_DIM: stim  = p; break;
            case G3 * IN_DIM:          W_ih  = p; break;
            case G3 * HID:             W_hh  = p; break;
            case RDIM * HID:           W_out = p; break;
            case RDIM:                 b_out = p; break;
            case G3:
                if (!b_ih) b_ih = p; else b_hh = p;
                break;
            default: break;
        }
    }
    if (!stim || !W_ih || !W_hh || !b_ih || !b_hh || !W_out || !b_out)
        return;

    float* g_hid_ptr;  cudaGetSymbolAddress((void**)&g_hid_ptr, g_hid);
    float* g_out_ptr;  cudaGetSymbolAddress((void**)&g_out_ptr, g_out);

    float* out;
    float* hid;
    if ((size_t)out_size >= TOT_N) {            // [out | rnn_hid]
        out = (float*)d_out;
        hid = (float*)d_out + OUT_N;
    } else if ((size_t)out_size >= HID_N) {
        hid = (float*)d_out;
        out = g_out_ptr;
    } else {
        out = (float*)d_out;
        hid = g_hid_ptr;
    }

    cudaFuncSetAttribute(gi_kernel,   cudaFuncAttributeMaxDynamicSharedMemorySize, GI_SMEM);
    cudaFuncSetAttribute(gru_kernel,  cudaFuncAttributeMaxDynamicSharedMemorySize, GRU_SMEM);
    cudaFuncSetAttribute(head_kernel, cudaFuncAttributeMaxDynamicSharedMemorySize, HD_SMEM);

    gi_kernel  <<<(BATCH * SEQ / GI_TBT) * 2, 512, GI_SMEM>>>(stim, W_ih, b_ih);
    gru_kernel <<<(BATCH / BT) * CLUSTER, 256, GRU_SMEM>>>(W_hh, b_hh, hid);
    head_kernel<<<(BATCH * SEQ) / HD_TBT, 256, HD_SMEM>>>(hid, W_out, b_out, out);
}